// round 7
// baseline (speedup 1.0000x reference)
#include <cuda_runtime.h>
#include <math.h>

#define BATCH 16
#define FH 192
#define FW 192
#define NA 9
#define NPI (FH*FW*NA)      /* 331776 anchors per image */
#define NPI4 (NPI/4)
#define PRE 6000
#define POST 1000
#define CAP 16384           /* candidate capacity per image (power of two for bitonic) */
#define HB 65536            /* histogram buckets = top 16 bits of fp32 score */
#define DEADID 0xFFFFu

// ---------------- device scratch (no allocations allowed) ----------------
__device__ unsigned int       g_hist[BATCH * HB];        // 4 MB (zeroed by k_thresh each pass)
__device__ unsigned int       g_cnt[BATCH];
__device__ int                g_thresh[BATCH];
__device__ unsigned long long g_keys[BATCH * CAP];       // 2 MB
__device__ float4             g_boxes[BATCH * PRE];      // 384 KB

// ---------------- kernel 1: score-bit histogram per image -----------------
__global__ void k_hist(const float* __restrict__ scores) {
    int b = blockIdx.y;
    const float4* s4 = (const float4*)(scores + (size_t)b * NPI);
    unsigned* h = g_hist + (size_t)b * HB;
    for (int i = blockIdx.x * blockDim.x + threadIdx.x; i < NPI4;
         i += gridDim.x * blockDim.x) {
        float4 v = s4[i];
        atomicAdd(&h[__float_as_uint(v.x) >> 16], 1u);
        atomicAdd(&h[__float_as_uint(v.y) >> 16], 1u);
        atomicAdd(&h[__float_as_uint(v.z) >> 16], 1u);
        atomicAdd(&h[__float_as_uint(v.w) >> 16], 1u);
    }
}

// ---------------- kernel 2: per-image threshold bucket + scratch reset ----
// Largest bucket T such that count(bucket >= T) >= PRE. Then zero hist/cnt
// for the next graph replay (runs before k_collect in the same replay).
__global__ void k_thresh() {
    int b = blockIdx.x;
    int t = threadIdx.x;               // 256 threads, each sums a 256-bucket chunk
    __shared__ unsigned csum[256];
    unsigned* h = g_hist + (size_t)b * HB;
    unsigned s = 0;
    int hi = HB - t * 256;
    for (int i = hi - 256; i < hi; i++) s += h[i];
    csum[t] = s;
    __syncthreads();
    if (t == 0) {
        unsigned cum = 0;
        int T = 0;
        for (int c = 0; c < 256; c++) {
            if (cum + csum[c] >= PRE) {
                int hi2 = HB - c * 256;
                for (int i = hi2 - 1;; i--) {
                    cum += h[i];
                    if (cum >= PRE) { T = i; break; }
                }
                break;
            }
            cum += csum[c];
        }
        g_thresh[b] = T;
        g_cnt[b] = 0u;                 // reset candidate counter for k_collect
    }
    __syncthreads();
    // zero this image's histogram for the next replay
    for (int i = t; i < HB; i += 256) h[i] = 0u;
}

// ---------------- kernel 3: collect candidate keys ------------------------
// key = (score_bits << 32) | (~idx): descending sort => score desc, then idx asc
// (matches lax.top_k stable tie-breaking exactly).
__global__ void k_collect(const float* __restrict__ scores) {
    int b = blockIdx.y;
    const float4* s4 = (const float4*)(scores + (size_t)b * NPI);
    int T = g_thresh[b];
    for (int i = blockIdx.x * blockDim.x + threadIdx.x; i < NPI4;
         i += gridDim.x * blockDim.x) {
        float4 v = s4[i];
        unsigned bw[4] = {__float_as_uint(v.x), __float_as_uint(v.y),
                          __float_as_uint(v.z), __float_as_uint(v.w)};
#pragma unroll
        for (int c = 0; c < 4; c++) {
            if ((int)(bw[c] >> 16) >= T) {
                unsigned pos = atomicAdd(&g_cnt[b], 1u);
                if (pos < CAP) {
                    unsigned idx = 4u * (unsigned)i + (unsigned)c;
                    g_keys[(size_t)b * CAP + pos] =
                        ((unsigned long long)bw[c] << 32) |
                        (unsigned long long)(0xFFFFFFFFu - idx);
                }
            }
        }
    }
}

// ---------------- kernel 4: per-image bitonic sort + decode ---------------
__global__ void k_sort_decode(const float* __restrict__ deltas,
                              const float* __restrict__ banch) {
    extern __shared__ unsigned long long sk[];   // CAP u64 = 128 KB
    __shared__ float sbase[NA * 4];
    int b = blockIdx.x, tid = threadIdx.x, bs = blockDim.x;

    unsigned cnt = g_cnt[b];
    if (cnt > CAP) cnt = CAP;
    for (int i = tid; i < CAP; i += bs)
        sk[i] = ((unsigned)i < cnt) ? g_keys[(size_t)b * CAP + i] : 0ull;
    if (tid < NA * 4) sbase[tid] = banch[tid];
    __syncthreads();

    // bitonic sort, descending
    for (int k = 2; k <= CAP; k <<= 1) {
        for (int j = k >> 1; j > 0; j >>= 1) {
            for (int i = tid; i < CAP; i += bs) {
                int ixj = i ^ j;
                if (ixj > i) {
                    unsigned long long a = sk[i], c = sk[ixj];
                    bool desc = ((i & k) == 0);
                    if (desc ? (a < c) : (a > c)) { sk[i] = c; sk[ixj] = a; }
                }
            }
            __syncthreads();
        }
    }

    // decode top PRE boxes (strict non-fused fp32 to track XLA rounding)
    for (int p = tid; p < PRE; p += bs) {
        unsigned long long key = sk[p];
        unsigned idx = 0xFFFFFFFFu - (unsigned)(key & 0xFFFFFFFFull);
        int a = idx % NA;
        int cell = idx / NA;
        int x = cell % FW;
        int y = cell / FW;
        float gy = __fdiv_rn((float)y + 0.5f, (float)FH);
        float gx = __fdiv_rn((float)x + 0.5f, (float)FW);
        float a0 = fminf(fmaxf(__fadd_rn(gy, sbase[a * 4 + 0]), 0.f), 1.f);
        float a1 = fminf(fmaxf(__fadd_rn(gx, sbase[a * 4 + 1]), 0.f), 1.f);
        float a2 = fminf(fmaxf(__fadd_rn(gy, sbase[a * 4 + 2]), 0.f), 1.f);
        float a3 = fminf(fmaxf(__fadd_rn(gx, sbase[a * 4 + 3]), 0.f), 1.f);
        const float* dp =
            deltas + ((((size_t)b * FH + y) * FW + x) * NA + a) * 4;
        float d0 = __fmul_rn(dp[0], 0.1f);
        float d1 = __fmul_rn(dp[1], 0.1f);
        float d2 = __fmul_rn(dp[2], 0.2f);
        float d3 = __fmul_rn(dp[3], 0.2f);
        float ah = __fsub_rn(a2, a0), aw = __fsub_rn(a3, a1);
        float acy = __fadd_rn(a0, __fmul_rn(0.5f, ah));
        float acx = __fadd_rn(a1, __fmul_rn(0.5f, aw));
        float eh = (float)exp((double)d2);   // correctly-rounded fp32 exp
        float ew = (float)exp((double)d3);
        float h = __fmul_rn(eh, ah);
        float w = __fmul_rn(ew, aw);
        float cy = __fadd_rn(__fmul_rn(d0, ah), acy);
        float cx = __fadd_rn(__fmul_rn(d1, aw), acx);
        float4 box;
        box.x = fminf(fmaxf(__fsub_rn(cy, __fmul_rn(0.5f, h)), 0.f), 1.f);
        box.y = fminf(fmaxf(__fsub_rn(cx, __fmul_rn(0.5f, w)), 0.f), 1.f);
        box.z = fminf(fmaxf(__fadd_rn(cy, __fmul_rn(0.5f, h)), 0.f), 1.f);
        box.w = fminf(fmaxf(__fadd_rn(cx, __fmul_rn(0.5f, w)), 0.f), 1.f);
        g_boxes[(size_t)b * PRE + p] = box;
    }
}

// ---------------- kernel 5: multi-select greedy NMS -----------------------
// Per round: one warp chain-selects up to 32 boxes (exact greedy order: a
// candidate is selected iff not suppressed by any in-round prior selection;
// all earlier-round suppressions are already applied to the list). Then one
// bulk sweep suppresses the remaining list against all new selections, and
// one compaction rebuilds the alive list. ~32 rounds instead of 1000.
#define NMS_SM_AREA  96000
#define NMS_SM_LST0  120000
#define NMS_SM_LST1  132000
#define NMS_SM_TOTAL 144000

// suppress <=> __fdiv_rn(inter, denom) > 0.7f; banded multiply gives the
// exact answer outside a +-7e-5 relative band (>> 1ulp of mul/div), rare
// exact fdiv fallback inside the band.
__device__ __forceinline__ bool iou_sup(float4 bi, float ai, float4 bj, float aj) {
    float yy1 = fmaxf(bi.x, bj.x);
    float xx1 = fmaxf(bi.y, bj.y);
    float yy2 = fminf(bi.z, bj.z);
    float xx2 = fminf(bi.w, bj.w);
    float ih = fmaxf(__fsub_rn(yy2, yy1), 0.f);
    float iw = fmaxf(__fsub_rn(xx2, xx1), 0.f);
    float inter = __fmul_rn(ih, iw);
    float denom = __fadd_rn(__fsub_rn(__fadd_rn(ai, aj), inter), 1e-8f);
    if (inter > __fmul_rn(denom, 0.7000500f)) return true;
    if (inter < __fmul_rn(denom, 0.6999500f)) return false;
    return __fdiv_rn(inter, denom) > 0.7f;
}

__global__ void k_nms(float* __restrict__ out) {
    extern __shared__ unsigned char sm[];
    float4* sb = (float4*)sm;
    float* sarea = (float*)(sm + NMS_SM_AREA);
    unsigned short* lst0 = (unsigned short*)(sm + NMS_SM_LST0);
    unsigned short* lst1 = (unsigned short*)(sm + NMS_SM_LST1);
    __shared__ float4 ssel[32];
    __shared__ float  sselarea[32];
    __shared__ int s_nsel, s_walk, s_cnt, s_total;
    __shared__ int s_warp[32];

    int b = blockIdx.x, tid = threadIdx.x, bs = blockDim.x;
    for (int i = tid; i < PRE; i += bs) {
        float4 v = g_boxes[(size_t)b * PRE + i];
        sb[i] = v;
        sarea[i] = __fmul_rn(fmaxf(__fsub_rn(v.z, v.x), 0.f),
                             fmaxf(__fsub_rn(v.w, v.y), 0.f));
        lst0[i] = (unsigned short)i;
    }
    if (tid == 0) s_cnt = PRE;
    int cur = 0;
    float4* orow4 = (float4*)(out + (size_t)b * POST * 4);
    __syncthreads();

    int k = 0;
    while (k < POST) {
        unsigned short* lst = cur ? lst1 : lst0;
        // ---- phase A: warp 0 chain-selects up to min(32, POST-k) boxes ----
        if (tid < 32) {
            int lane = tid;
            int cnt = s_cnt;
            int lim = POST - k; if (lim > 32) lim = 32;
            int nsel = 0, p = 0;
            while (nsel < lim && p < cnt) {
                int id = lst[p];
                float4 bj = sb[id];
                float aj = sarea[id];
                bool sup = false;
                if (lane < nsel)
                    sup = iou_sup(ssel[lane], sselarea[lane], bj, aj);
                unsigned m = __ballot_sync(0xffffffffu, sup);
                if (m == 0) {
                    if (lane == 0) {
                        ssel[nsel] = bj;
                        sselarea[nsel] = aj;
                        orow4[k + nsel] = bj;
                        lst[p] = DEADID;
                    }
                    nsel++;
                } else {
                    if (lane == 0) lst[p] = DEADID;
                }
                __syncwarp();
                p++;
            }
            if (lane == 0) { s_nsel = nsel; s_walk = p; }
        }
        __syncthreads();
        int nsel = s_nsel;
        if (nsel == 0) break;
        int cnt = s_cnt;
        int walk = s_walk;

        // ---- phase B: bulk sweep remaining list vs all new selections ----
        for (int p = walk + tid; p < cnt; p += bs) {
            int id = lst[p];
            float4 bj = sb[id];
            float aj = sarea[id];
            bool dead = false;
            for (int s = 0; s < nsel; s++) {
                if (iou_sup(ssel[s], sselarea[s], bj, aj)) { dead = true; break; }
            }
            if (dead) lst[p] = DEADID;
        }
        __syncthreads();

        // ---- phase C: compact alive ids into the other buffer ----
        {
            int per = (cnt + bs - 1) / bs;          // <= 6
            int st = tid * per;
            int en = st + per; if (en > cnt) en = cnt;
            unsigned short tmp[6];
            int c = 0;
            for (int p = st; p < en; p++) {
                unsigned short id = lst[p];
                if (id != DEADID) tmp[c++] = id;
            }
            int lane = tid & 31, wid = tid >> 5;
            int incl = c;
            for (int d = 1; d < 32; d <<= 1) {
                int t = __shfl_up_sync(0xffffffffu, incl, d);
                if (lane >= d) incl += t;
            }
            if (lane == 31) s_warp[wid] = incl;
            __syncthreads();
            if (wid == 0) {
                int v = s_warp[lane];
                int wi = v;
                for (int d = 1; d < 32; d <<= 1) {
                    int t = __shfl_up_sync(0xffffffffu, wi, d);
                    if (lane >= d) wi += t;
                }
                s_warp[lane] = wi - v;              // exclusive warp offset
                if (lane == 31) s_total = wi;
            }
            __syncthreads();
            int off = s_warp[wid] + (incl - c);
            unsigned short* dst = cur ? lst0 : lst1;
            for (int i2 = 0; i2 < c; i2++) dst[off + i2] = tmp[i2];
            __syncthreads();
            if (tid == 0) s_cnt = s_total;
            cur ^= 1;
            __syncthreads();
        }
        k += nsel;
    }
    // zero-pad remaining outputs (reference pads with zeros)
    for (int idx = k * 4 + tid; idx < POST * 4; idx += bs)
        out[(size_t)b * POST * 4 + idx] = 0.0f;
}

// ---------------- launch ---------------------------------------------------
extern "C" void kernel_launch(void* const* d_in, const int* in_sizes, int n_in,
                              void* d_out, int out_size) {
    const float* deltas = (const float*)d_in[0];   // (16,192,192,36)
    const float* scores = (const float*)d_in[1];   // (16,192,192,9)
    const float* banch  = (const float*)d_in[2];   // (9,4)
    float* out = (float*)d_out;                    // (16,1000,4)

    cudaFuncSetAttribute(k_sort_decode,
                         cudaFuncAttributeMaxDynamicSharedMemorySize,
                         CAP * (int)sizeof(unsigned long long));
    cudaFuncSetAttribute(k_nms,
                         cudaFuncAttributeMaxDynamicSharedMemorySize,
                         NMS_SM_TOTAL);

    dim3 grid2(108, BATCH);                         // ~3 float4 per thread
    k_hist<<<grid2, 256>>>(scores);
    k_thresh<<<BATCH, 256>>>();
    k_collect<<<grid2, 256>>>(scores);
    k_sort_decode<<<BATCH, 1024, CAP * (int)sizeof(unsigned long long)>>>(
        deltas, banch);
    k_nms<<<BATCH, 1024, NMS_SM_TOTAL>>>(out);
}

// round 8
// speedup vs baseline: 1.0066x; 1.0066x over previous
#include <cuda_runtime.h>
#include <math.h>

#define BATCH 16
#define FH 192
#define FW 192
#define NA 9
#define NPI (FH*FW*NA)      /* 331776 anchors per image */
#define NPI4 (NPI/4)        /* 82944 */
#define PRE 6000
#define POST 1000
#define CAP 8192            /* candidate capacity per image (power of two for bitonic) */
#define HB 65536            /* histogram buckets = top 16 bits of fp32 score */
#define DEADID 0xFFFFu
#define NMSW 512            /* NMS window size */

// ---------------- device scratch (no allocations allowed) ----------------
__device__ unsigned int       g_hist[BATCH * HB];        // 4 MB (zeroed by k_collect each pass)
__device__ unsigned int       g_cnt[BATCH];
__device__ int                g_thresh[BATCH];
__device__ unsigned long long g_keys[BATCH * CAP];       // 1 MB
__device__ float4             g_boxes[BATCH * PRE];      // 384 KB

// ---------------- kernel 1: score-bit histogram per image -----------------
// grid (81, BATCH) x 256: exactly 4 float4 per thread, batched for MLP.
__global__ void k_hist(const float* __restrict__ scores) {
    int b = blockIdx.y;
    const float4* s4 = (const float4*)(scores + (size_t)b * NPI);
    unsigned* h = g_hist + (size_t)b * HB;
    int i = blockIdx.x * blockDim.x + threadIdx.x;
    int step = gridDim.x * blockDim.x;                  // 20736 = NPI4/4
    float4 v0 = s4[i];
    float4 v1 = s4[i + step];
    float4 v2 = s4[i + 2 * step];
    float4 v3 = s4[i + 3 * step];
    atomicAdd(&h[__float_as_uint(v0.x) >> 16], 1u);
    atomicAdd(&h[__float_as_uint(v0.y) >> 16], 1u);
    atomicAdd(&h[__float_as_uint(v0.z) >> 16], 1u);
    atomicAdd(&h[__float_as_uint(v0.w) >> 16], 1u);
    atomicAdd(&h[__float_as_uint(v1.x) >> 16], 1u);
    atomicAdd(&h[__float_as_uint(v1.y) >> 16], 1u);
    atomicAdd(&h[__float_as_uint(v1.z) >> 16], 1u);
    atomicAdd(&h[__float_as_uint(v1.w) >> 16], 1u);
    atomicAdd(&h[__float_as_uint(v2.x) >> 16], 1u);
    atomicAdd(&h[__float_as_uint(v2.y) >> 16], 1u);
    atomicAdd(&h[__float_as_uint(v2.z) >> 16], 1u);
    atomicAdd(&h[__float_as_uint(v2.w) >> 16], 1u);
    atomicAdd(&h[__float_as_uint(v3.x) >> 16], 1u);
    atomicAdd(&h[__float_as_uint(v3.y) >> 16], 1u);
    atomicAdd(&h[__float_as_uint(v3.z) >> 16], 1u);
    atomicAdd(&h[__float_as_uint(v3.w) >> 16], 1u);
}

// ---------------- kernel 2: per-image threshold bucket --------------------
// Largest bucket T such that count(bucket >= T) >= PRE; resets g_cnt.
__global__ void k_thresh() {
    int b = blockIdx.x;
    int t = threadIdx.x;               // 256 threads, each sums a 256-bucket chunk
    __shared__ unsigned csum[256];
    unsigned* h = g_hist + (size_t)b * HB;
    unsigned s = 0;
    int hi = HB - t * 256;
    for (int i = hi - 256; i < hi; i++) s += h[i];
    csum[t] = s;
    __syncthreads();
    if (t == 0) {
        unsigned cum = 0;
        int T = 0;
        for (int c = 0; c < 256; c++) {
            if (cum + csum[c] >= PRE) {
                int hi2 = HB - c * 256;
                for (int i = hi2 - 1;; i--) {
                    cum += h[i];
                    if (cum >= PRE) { T = i; break; }
                }
                break;
            }
            cum += csum[c];
        }
        g_thresh[b] = T;
        g_cnt[b] = 0u;                 // reset candidate counter for k_collect
    }
}

// ---------------- kernel 3: collect candidate keys + zero histogram -------
// key = (score_bits << 32) | (~idx): descending sort => score desc, then idx asc
// (matches lax.top_k stable tie-breaking exactly). Also zeroes this image's
// histogram for the next graph replay (runs after k_thresh consumed it).
__global__ void k_collect(const float* __restrict__ scores) {
    int b = blockIdx.y;
    const float4* s4 = (const float4*)(scores + (size_t)b * NPI);
    int T = g_thresh[b];
    int i = blockIdx.x * blockDim.x + threadIdx.x;
    int step = gridDim.x * blockDim.x;                  // 20736
    float4 v[4];
    v[0] = s4[i]; v[1] = s4[i + step]; v[2] = s4[i + 2 * step];
    v[3] = s4[i + 3 * step];
#pragma unroll
    for (int q = 0; q < 4; q++) {
        unsigned bw[4] = {__float_as_uint(v[q].x), __float_as_uint(v[q].y),
                          __float_as_uint(v[q].z), __float_as_uint(v[q].w)};
#pragma unroll
        for (int c = 0; c < 4; c++) {
            if ((int)(bw[c] >> 16) >= T) {
                unsigned pos = atomicAdd(&g_cnt[b], 1u);
                if (pos < CAP) {
                    unsigned idx = 4u * (unsigned)(i + q * step) + (unsigned)c;
                    g_keys[(size_t)b * CAP + pos] =
                        ((unsigned long long)bw[c] << 32) |
                        (unsigned long long)(0xFFFFFFFFu - idx);
                }
            }
        }
    }
    // zero histogram for next replay
    unsigned* h = g_hist + (size_t)b * HB;
    for (int j = i; j < HB; j += step) h[j] = 0u;
}

// ---------------- kernel 4: per-image bitonic sort + decode ---------------
__global__ __launch_bounds__(1024) void k_sort_decode(
        const float* __restrict__ deltas, const float* __restrict__ banch) {
    extern __shared__ unsigned long long sk[];   // CAP u64 = 64 KB
    __shared__ float sbase[NA * 4];
    int b = blockIdx.x, tid = threadIdx.x, bs = blockDim.x;

    unsigned cnt = g_cnt[b];
    if (cnt > CAP) cnt = CAP;
    for (int i = tid; i < CAP; i += bs)
        sk[i] = ((unsigned)i < cnt) ? g_keys[(size_t)b * CAP + i] : 0ull;
    if (tid < NA * 4) sbase[tid] = banch[tid];
    __syncthreads();

    // bitonic sort, descending
    for (int k = 2; k <= CAP; k <<= 1) {
        for (int j = k >> 1; j > 0; j >>= 1) {
            for (int i = tid; i < CAP; i += bs) {
                int ixj = i ^ j;
                if (ixj > i) {
                    unsigned long long a = sk[i], c = sk[ixj];
                    bool desc = ((i & k) == 0);
                    if (desc ? (a < c) : (a > c)) { sk[i] = c; sk[ixj] = a; }
                }
            }
            __syncthreads();
        }
    }

    // decode top PRE boxes (strict non-fused fp32 to track XLA rounding)
    for (int p = tid; p < PRE; p += bs) {
        unsigned long long key = sk[p];
        unsigned idx = 0xFFFFFFFFu - (unsigned)(key & 0xFFFFFFFFull);
        int a = idx % NA;
        int cell = idx / NA;
        int x = cell % FW;
        int y = cell / FW;
        float gy = __fdiv_rn((float)y + 0.5f, (float)FH);
        float gx = __fdiv_rn((float)x + 0.5f, (float)FW);
        float a0 = fminf(fmaxf(__fadd_rn(gy, sbase[a * 4 + 0]), 0.f), 1.f);
        float a1 = fminf(fmaxf(__fadd_rn(gx, sbase[a * 4 + 1]), 0.f), 1.f);
        float a2 = fminf(fmaxf(__fadd_rn(gy, sbase[a * 4 + 2]), 0.f), 1.f);
        float a3 = fminf(fmaxf(__fadd_rn(gx, sbase[a * 4 + 3]), 0.f), 1.f);
        const float* dp =
            deltas + ((((size_t)b * FH + y) * FW + x) * NA + a) * 4;
        float d0 = __fmul_rn(dp[0], 0.1f);
        float d1 = __fmul_rn(dp[1], 0.1f);
        float d2 = __fmul_rn(dp[2], 0.2f);
        float d3 = __fmul_rn(dp[3], 0.2f);
        float ah = __fsub_rn(a2, a0), aw = __fsub_rn(a3, a1);
        float acy = __fadd_rn(a0, __fmul_rn(0.5f, ah));
        float acx = __fadd_rn(a1, __fmul_rn(0.5f, aw));
        float eh = (float)exp((double)d2);   // correctly-rounded fp32 exp
        float ew = (float)exp((double)d3);
        float h = __fmul_rn(eh, ah);
        float w = __fmul_rn(ew, aw);
        float cy = __fadd_rn(__fmul_rn(d0, ah), acy);
        float cx = __fadd_rn(__fmul_rn(d1, aw), acx);
        float4 box;
        box.x = fminf(fmaxf(__fsub_rn(cy, __fmul_rn(0.5f, h)), 0.f), 1.f);
        box.y = fminf(fmaxf(__fsub_rn(cx, __fmul_rn(0.5f, w)), 0.f), 1.f);
        box.z = fminf(fmaxf(__fadd_rn(cy, __fmul_rn(0.5f, h)), 0.f), 1.f);
        box.w = fminf(fmaxf(__fadd_rn(cx, __fmul_rn(0.5f, w)), 0.f), 1.f);
        g_boxes[(size_t)b * PRE + p] = box;
    }
}

// ---------------- kernel 5: window-bitmask greedy NMS ---------------------
// Per round: stage first W alive entries, build the WxW upper-triangular
// suppression matrix in parallel (bitmasks), run the greedy chain as pure
// bit ops on tid0 (exact greedy order), bulk-sweep the rest of the list
// against all new selections, compact. ~5-12 rounds total.
#define NMS_SB    0                         /* float4[PRE]  96000 */
#define NMS_SAREA 96000                     /* float[PRE]   24000 */
#define NMS_LST0  120000                    /* u16[PRE]     12000 */
#define NMS_LST1  132000                    /* u16[PRE]     12000 */
#define NMS_WB    144000                    /* float4[W]     8192 */
#define NMS_WA    152192                    /* float[W]      2048 */
#define NMS_SUP   154240                    /* u32[W*16]    32768 */
#define NMS_SPOS  187008                    /* u16[W]        1024 */
#define NMS_TOTAL 188032

// suppress <=> __fdiv_rn(inter, denom) > 0.7f; banded multiply gives the
// exact answer outside a +-7e-5 relative band (>> 1ulp of mul/div), rare
// exact fdiv fallback inside the band.
__device__ __forceinline__ bool iou_sup(float4 bi, float ai, float4 bj, float aj) {
    float yy1 = fmaxf(bi.x, bj.x);
    float xx1 = fmaxf(bi.y, bj.y);
    float yy2 = fminf(bi.z, bj.z);
    float xx2 = fminf(bi.w, bj.w);
    float ih = fmaxf(__fsub_rn(yy2, yy1), 0.f);
    float iw = fmaxf(__fsub_rn(xx2, xx1), 0.f);
    float inter = __fmul_rn(ih, iw);
    float denom = __fadd_rn(__fsub_rn(__fadd_rn(ai, aj), inter), 1e-8f);
    if (inter > __fmul_rn(denom, 0.7000500f)) return true;
    if (inter < __fmul_rn(denom, 0.6999500f)) return false;
    return __fdiv_rn(inter, denom) > 0.7f;
}

__global__ __launch_bounds__(1024) void k_nms(float* __restrict__ out) {
    extern __shared__ unsigned char sm[];
    float4* sb = (float4*)(sm + NMS_SB);
    float* sarea = (float*)(sm + NMS_SAREA);
    unsigned short* lst0 = (unsigned short*)(sm + NMS_LST0);
    unsigned short* lst1 = (unsigned short*)(sm + NMS_LST1);
    float4* wb = (float4*)(sm + NMS_WB);
    float* wa = (float*)(sm + NMS_WA);
    unsigned* sup = (unsigned*)(sm + NMS_SUP);
    unsigned short* spos = (unsigned short*)(sm + NMS_SPOS);
    __shared__ int s_nsel, s_cnt, s_total;
    __shared__ int s_warp[32];

    int b = blockIdx.x, tid = threadIdx.x, bs = blockDim.x;
    for (int i = tid; i < PRE; i += bs) {
        float4 v = g_boxes[(size_t)b * PRE + i];
        sb[i] = v;
        sarea[i] = __fmul_rn(fmaxf(__fsub_rn(v.z, v.x), 0.f),
                             fmaxf(__fsub_rn(v.w, v.y), 0.f));
        lst0[i] = (unsigned short)i;
    }
    if (tid == 0) s_cnt = PRE;
    int cur = 0;
    float4* orow4 = (float4*)(out + (size_t)b * POST * 4);
    __syncthreads();

    int k = 0;
    while (k < POST) {
        int cnt = s_cnt;
        if (cnt == 0) break;
        unsigned short* lst = cur ? lst1 : lst0;
        int w = cnt < NMSW ? cnt : NMSW;

        // ---- stage window boxes contiguously ----
        if (tid < w) {
            int id = lst[tid];
            wb[tid] = sb[id];
            wa[tid] = sarea[id];
        }
        __syncthreads();

        // ---- parallel suppression matrix: row p, bit q set (q>p) if p sups q
        for (int cell = tid; cell < w * 16; cell += bs) {
            int p = cell >> 4;
            int wd = cell & 15;
            unsigned m = 0;
            int qbase = wd << 5;
            if (qbase + 31 > p) {               // word intersects q>p region
                float4 bp = wb[p];
                float ap = wa[p];
#pragma unroll 8
                for (int t = 0; t < 32; t++) {
                    int q = qbase + t;
                    if (q > p && q < w && iou_sup(bp, ap, wb[q], wa[q]))
                        m |= 1u << t;
                }
            }
            sup[cell] = m;
        }
        __syncthreads();

        // ---- greedy chain as bit ops (tid 0) ----
        if (tid == 0) {
            int nsel = 0;
            int lim = POST - k;
            for (int wd = 0; (wd << 5) < w && nsel < lim; wd++) {
                unsigned dead = 0;
                for (int s = 0; s < nsel; s++)
                    dead |= sup[((int)spos[s] << 4) + wd];
                int hi = w - (wd << 5);
                unsigned valid = (hi >= 32) ? 0xffffffffu : ((1u << hi) - 1u);
                unsigned alive = ~dead & valid;
                while (alive) {
                    int bit = __ffs(alive) - 1;
                    int p = (wd << 5) + bit;
                    spos[nsel++] = (unsigned short)p;
                    if (nsel >= lim) break;
                    dead |= sup[(p << 4) + wd] | (1u << bit);
                    alive = ~dead & valid;
                }
                if (nsel >= lim) break;
            }
            s_nsel = nsel;
        }
        __syncthreads();
        int nsel = s_nsel;

        // ---- write outputs; compact selected boxes to wb[0..nsel) ----
        float4 selb; float sela;
        if (tid < nsel) {
            int p = spos[tid];
            selb = wb[p];
            sela = wa[p];
            orow4[k + tid] = selb;
        }
        __syncthreads();
        if (tid < nsel) { wb[tid] = selb; wa[tid] = sela; }
        k += nsel;
        if (k >= POST) break;
        __syncthreads();

        // ---- bulk sweep rest of list vs all new selections ----
        for (int pos = w + tid; pos < cnt; pos += bs) {
            int id = lst[pos];
            float4 bj = sb[id];
            float aj = sarea[id];
            bool dead = false;
            for (int s = 0; s < nsel; s++) {
                if (iou_sup(wb[s], wa[s], bj, aj)) { dead = true; break; }
            }
            if (dead) lst[pos] = DEADID;
        }
        __syncthreads();

        // ---- compact alive ids from [w,cnt) into the other buffer ----
        {
            int n = cnt - w;
            int per = (n + bs - 1) / bs;            // <= 6
            int st = w + tid * per;
            int en = st + per; if (en > cnt) en = cnt;
            unsigned short tmp[6];
            int c = 0;
            for (int p = st; p < en; p++) {
                unsigned short id = lst[p];
                if (id != DEADID) tmp[c++] = id;
            }
            int lane = tid & 31, wid = tid >> 5;
            int incl = c;
            for (int d = 1; d < 32; d <<= 1) {
                int t = __shfl_up_sync(0xffffffffu, incl, d);
                if (lane >= d) incl += t;
            }
            if (lane == 31) s_warp[wid] = incl;
            __syncthreads();
            if (wid == 0) {
                int v = s_warp[lane];
                int wi = v;
                for (int d = 1; d < 32; d <<= 1) {
                    int t = __shfl_up_sync(0xffffffffu, wi, d);
                    if (lane >= d) wi += t;
                }
                s_warp[lane] = wi - v;              // exclusive warp offset
                if (lane == 31) s_total = wi;
            }
            __syncthreads();
            int off = s_warp[wid] + (incl - c);
            unsigned short* dst = cur ? lst0 : lst1;
            for (int i2 = 0; i2 < c; i2++) dst[off + i2] = tmp[i2];
            __syncthreads();
            if (tid == 0) s_cnt = s_total;
            cur ^= 1;
            __syncthreads();
        }
    }
    // zero-pad remaining outputs (reference pads with zeros)
    for (int idx = k * 4 + tid; idx < POST * 4; idx += bs)
        out[(size_t)b * POST * 4 + idx] = 0.0f;
}

// ---------------- launch ---------------------------------------------------
extern "C" void kernel_launch(void* const* d_in, const int* in_sizes, int n_in,
                              void* d_out, int out_size) {
    const float* deltas = (const float*)d_in[0];   // (16,192,192,36)
    const float* scores = (const float*)d_in[1];   // (16,192,192,9)
    const float* banch  = (const float*)d_in[2];   // (9,4)
    float* out = (float*)d_out;                    // (16,1000,4)

    cudaFuncSetAttribute(k_sort_decode,
                         cudaFuncAttributeMaxDynamicSharedMemorySize,
                         CAP * (int)sizeof(unsigned long long));
    cudaFuncSetAttribute(k_nms,
                         cudaFuncAttributeMaxDynamicSharedMemorySize,
                         NMS_TOTAL);

    dim3 grid2(81, BATCH);                         // exactly 4 float4/thread
    k_hist<<<grid2, 256>>>(scores);
    k_thresh<<<BATCH, 256>>>();
    k_collect<<<grid2, 256>>>(scores);
    k_sort_decode<<<BATCH, 1024, CAP * (int)sizeof(unsigned long long)>>>(
        deltas, banch);
    k_nms<<<BATCH, 1024, NMS_TOTAL>>>(out);
}

// round 9
// speedup vs baseline: 1.1442x; 1.1367x over previous
#include <cuda_runtime.h>
#include <math.h>

#define BATCH 16
#define FH 192
#define FW 192
#define NA 9
#define NPI (FH*FW*NA)      /* 331776 anchors per image */
#define NPI4 (NPI/4)        /* 82944 */
#define PRE 6000
#define POST 1000
#define CAP 8192            /* candidate capacity per image (power of two for bitonic) */
#define HB 65536            /* histogram buckets = top 16 bits of fp32 score */
#define DEADID 0xFFFFu
#define NMSW 128            /* NMS window size (4 mask words) */

// ---------------- device scratch (no allocations allowed) ----------------
__device__ unsigned int       g_hist[BATCH * HB];        // 4 MB (zeroed by k_collect each pass)
__device__ unsigned int       g_cnt[BATCH];
__device__ int                g_thresh[BATCH];
__device__ unsigned long long g_keys[BATCH * CAP];       // 1 MB
__device__ float4             g_boxes[BATCH * PRE];      // 384 KB

// ---------------- kernel 1: score-bit histogram per image -----------------
// grid (81, BATCH) x 256: exactly 4 float4 per thread, batched for MLP.
__global__ void k_hist(const float* __restrict__ scores) {
    int b = blockIdx.y;
    const float4* s4 = (const float4*)(scores + (size_t)b * NPI);
    unsigned* h = g_hist + (size_t)b * HB;
    int i = blockIdx.x * blockDim.x + threadIdx.x;
    int step = gridDim.x * blockDim.x;                  // 20736 = NPI4/4
    float4 v0 = s4[i];
    float4 v1 = s4[i + step];
    float4 v2 = s4[i + 2 * step];
    float4 v3 = s4[i + 3 * step];
    atomicAdd(&h[__float_as_uint(v0.x) >> 16], 1u);
    atomicAdd(&h[__float_as_uint(v0.y) >> 16], 1u);
    atomicAdd(&h[__float_as_uint(v0.z) >> 16], 1u);
    atomicAdd(&h[__float_as_uint(v0.w) >> 16], 1u);
    atomicAdd(&h[__float_as_uint(v1.x) >> 16], 1u);
    atomicAdd(&h[__float_as_uint(v1.y) >> 16], 1u);
    atomicAdd(&h[__float_as_uint(v1.z) >> 16], 1u);
    atomicAdd(&h[__float_as_uint(v1.w) >> 16], 1u);
    atomicAdd(&h[__float_as_uint(v2.x) >> 16], 1u);
    atomicAdd(&h[__float_as_uint(v2.y) >> 16], 1u);
    atomicAdd(&h[__float_as_uint(v2.z) >> 16], 1u);
    atomicAdd(&h[__float_as_uint(v2.w) >> 16], 1u);
    atomicAdd(&h[__float_as_uint(v3.x) >> 16], 1u);
    atomicAdd(&h[__float_as_uint(v3.y) >> 16], 1u);
    atomicAdd(&h[__float_as_uint(v3.z) >> 16], 1u);
    atomicAdd(&h[__float_as_uint(v3.w) >> 16], 1u);
}

// ---------------- kernel 2: per-image threshold bucket --------------------
// Largest bucket T such that count(bucket >= T) >= PRE; resets g_cnt.
// Chunk scan on tid0 is smem-only; in-chunk refinement is a parallel
// suffix-scan (no serial global-latency chain).
__global__ void k_thresh() {
    int b = blockIdx.x;
    int t = threadIdx.x;               // 256 threads, each sums a 256-bucket chunk
    __shared__ unsigned csum[256];
    __shared__ unsigned sbuf[256];
    __shared__ unsigned sfin[256];
    __shared__ int s_chunk;
    __shared__ unsigned s_above;
    const unsigned* h = g_hist + (size_t)b * HB;
    int base = t * 256;
    unsigned s = 0;
    for (int i = 0; i < 256; i++) s += h[base + i];
    csum[t] = s;
    __syncthreads();
    if (t == 0) {
        unsigned cum = 0;
        int c = 255;
        for (; c >= 0; c--) {
            if (cum + csum[c] >= PRE) break;
            cum += csum[c];
        }
        s_chunk = c;
        s_above = cum;                 // count strictly above chunk c
        g_cnt[b] = 0u;                 // reset candidate counter for k_collect
    }
    __syncthreads();
    int c = s_chunk;
    unsigned above = s_above;
    sbuf[t] = h[c * 256 + t];
    __syncthreads();
    // inclusive suffix sum (Hillis-Steele)
    for (int d = 1; d < 256; d <<= 1) {
        unsigned v = (t + d < 256) ? sbuf[t + d] : 0u;
        __syncthreads();
        sbuf[t] += v;
        __syncthreads();
    }
    sfin[t] = sbuf[t];
    __syncthreads();
    // largest index i with suffix(i)+above >= PRE (suffix is non-increasing)
    bool ok = (sfin[t] + above >= PRE);
    bool next_ok = (t < 255) ? (sfin[t + 1] + above >= PRE) : false;
    if (ok && !next_ok) g_thresh[b] = c * 256 + t;
}

// ---------------- kernel 3: collect candidate keys + zero histogram -------
// key = (score_bits << 32) | (~idx): descending sort => score desc, then idx asc
// (matches lax.top_k stable tie-breaking exactly). Also zeroes this image's
// histogram for the next graph replay (runs after k_thresh consumed it).
__global__ void k_collect(const float* __restrict__ scores) {
    int b = blockIdx.y;
    const float4* s4 = (const float4*)(scores + (size_t)b * NPI);
    int T = g_thresh[b];
    int i = blockIdx.x * blockDim.x + threadIdx.x;
    int step = gridDim.x * blockDim.x;                  // 20736
    float4 v[4];
    v[0] = s4[i]; v[1] = s4[i + step]; v[2] = s4[i + 2 * step];
    v[3] = s4[i + 3 * step];
#pragma unroll
    for (int q = 0; q < 4; q++) {
        unsigned bw[4] = {__float_as_uint(v[q].x), __float_as_uint(v[q].y),
                          __float_as_uint(v[q].z), __float_as_uint(v[q].w)};
#pragma unroll
        for (int c = 0; c < 4; c++) {
            if ((int)(bw[c] >> 16) >= T) {
                unsigned pos = atomicAdd(&g_cnt[b], 1u);
                if (pos < CAP) {
                    unsigned idx = 4u * (unsigned)(i + q * step) + (unsigned)c;
                    g_keys[(size_t)b * CAP + pos] =
                        ((unsigned long long)bw[c] << 32) |
                        (unsigned long long)(0xFFFFFFFFu - idx);
                }
            }
        }
    }
    // zero histogram for next replay
    unsigned* h = g_hist + (size_t)b * HB;
    for (int j = i; j < HB; j += step) h[j] = 0u;
}

// ---------------- kernel 4: per-image bitonic sort + decode ---------------
__global__ __launch_bounds__(1024) void k_sort_decode(
        const float* __restrict__ deltas, const float* __restrict__ banch) {
    extern __shared__ unsigned long long sk[];   // CAP u64 = 64 KB
    __shared__ float sbase[NA * 4];
    int b = blockIdx.x, tid = threadIdx.x, bs = blockDim.x;

    unsigned cnt = g_cnt[b];
    if (cnt > CAP) cnt = CAP;
    for (int i = tid; i < CAP; i += bs)
        sk[i] = ((unsigned)i < cnt) ? g_keys[(size_t)b * CAP + i] : 0ull;
    if (tid < NA * 4) sbase[tid] = banch[tid];
    __syncthreads();

    // bitonic sort, descending
    for (int k = 2; k <= CAP; k <<= 1) {
        for (int j = k >> 1; j > 0; j >>= 1) {
            for (int i = tid; i < CAP; i += bs) {
                int ixj = i ^ j;
                if (ixj > i) {
                    unsigned long long a = sk[i], c = sk[ixj];
                    bool desc = ((i & k) == 0);
                    if (desc ? (a < c) : (a > c)) { sk[i] = c; sk[ixj] = a; }
                }
            }
            __syncthreads();
        }
    }

    // decode top PRE boxes (strict non-fused fp32 to track XLA rounding)
    for (int p = tid; p < PRE; p += bs) {
        unsigned long long key = sk[p];
        unsigned idx = 0xFFFFFFFFu - (unsigned)(key & 0xFFFFFFFFull);
        int a = idx % NA;
        int cell = idx / NA;
        int x = cell % FW;
        int y = cell / FW;
        float gy = __fdiv_rn((float)y + 0.5f, (float)FH);
        float gx = __fdiv_rn((float)x + 0.5f, (float)FW);
        float a0 = fminf(fmaxf(__fadd_rn(gy, sbase[a * 4 + 0]), 0.f), 1.f);
        float a1 = fminf(fmaxf(__fadd_rn(gx, sbase[a * 4 + 1]), 0.f), 1.f);
        float a2 = fminf(fmaxf(__fadd_rn(gy, sbase[a * 4 + 2]), 0.f), 1.f);
        float a3 = fminf(fmaxf(__fadd_rn(gx, sbase[a * 4 + 3]), 0.f), 1.f);
        const float* dp =
            deltas + ((((size_t)b * FH + y) * FW + x) * NA + a) * 4;
        float d0 = __fmul_rn(dp[0], 0.1f);
        float d1 = __fmul_rn(dp[1], 0.1f);
        float d2 = __fmul_rn(dp[2], 0.2f);
        float d3 = __fmul_rn(dp[3], 0.2f);
        float ah = __fsub_rn(a2, a0), aw = __fsub_rn(a3, a1);
        float acy = __fadd_rn(a0, __fmul_rn(0.5f, ah));
        float acx = __fadd_rn(a1, __fmul_rn(0.5f, aw));
        float eh = (float)exp((double)d2);   // correctly-rounded fp32 exp
        float ew = (float)exp((double)d3);
        float h = __fmul_rn(eh, ah);
        float w = __fmul_rn(ew, aw);
        float cy = __fadd_rn(__fmul_rn(d0, ah), acy);
        float cx = __fadd_rn(__fmul_rn(d1, aw), acx);
        float4 box;
        box.x = fminf(fmaxf(__fsub_rn(cy, __fmul_rn(0.5f, h)), 0.f), 1.f);
        box.y = fminf(fmaxf(__fsub_rn(cx, __fmul_rn(0.5f, w)), 0.f), 1.f);
        box.z = fminf(fmaxf(__fadd_rn(cy, __fmul_rn(0.5f, h)), 0.f), 1.f);
        box.w = fminf(fmaxf(__fadd_rn(cx, __fmul_rn(0.5f, w)), 0.f), 1.f);
        g_boxes[(size_t)b * PRE + p] = box;
    }
}

// ---------------- kernel 5: small-window bitmask greedy NMS ---------------
// W=128 window: tiny suppression matrix (128x4 words) built in parallel,
// warp-parallel greedy chain (4 lanes hold the dead mask; one parallel LDS
// per selection), bulk sweep vs new selections, compaction. Round cost is
// small and insensitive to the in-window suppression rate.
#define NMS_SB    0                         /* float4[PRE]   96000 */
#define NMS_SAREA 96000                     /* float[PRE]    24000 */
#define NMS_LST0  120000                    /* u16[PRE]      12000 */
#define NMS_LST1  132000                    /* u16[PRE]      12000 */
#define NMS_WB    144000                    /* float4[W]      2048 */
#define NMS_WA    146048                    /* float[W]        512 */
#define NMS_SSEL  146560                    /* float4[W]      2048 */
#define NMS_SSA   148608                    /* float[W]        512 */
#define NMS_SUP   149120                    /* u32[W*4]       2048 */
#define NMS_SPOS  151168                    /* u16[W]          256 */
#define NMS_TOTAL 151424

// suppress <=> __fdiv_rn(inter, denom) > 0.7f; banded multiply gives the
// exact answer outside a +-7e-5 relative band (>> 1ulp of mul/div), rare
// exact fdiv fallback inside the band.
__device__ __forceinline__ bool iou_sup(float4 bi, float ai, float4 bj, float aj) {
    float yy1 = fmaxf(bi.x, bj.x);
    float xx1 = fmaxf(bi.y, bj.y);
    float yy2 = fminf(bi.z, bj.z);
    float xx2 = fminf(bi.w, bj.w);
    float ih = fmaxf(__fsub_rn(yy2, yy1), 0.f);
    float iw = fmaxf(__fsub_rn(xx2, xx1), 0.f);
    float inter = __fmul_rn(ih, iw);
    float denom = __fadd_rn(__fsub_rn(__fadd_rn(ai, aj), inter), 1e-8f);
    if (inter > __fmul_rn(denom, 0.7000500f)) return true;
    if (inter < __fmul_rn(denom, 0.6999500f)) return false;
    return __fdiv_rn(inter, denom) > 0.7f;
}

__global__ __launch_bounds__(1024) void k_nms(float* __restrict__ out) {
    extern __shared__ unsigned char sm[];
    float4* sb = (float4*)(sm + NMS_SB);
    float* sarea = (float*)(sm + NMS_SAREA);
    unsigned short* lst0 = (unsigned short*)(sm + NMS_LST0);
    unsigned short* lst1 = (unsigned short*)(sm + NMS_LST1);
    float4* wb = (float4*)(sm + NMS_WB);
    float* wa = (float*)(sm + NMS_WA);
    float4* ssel = (float4*)(sm + NMS_SSEL);
    float* ssa = (float*)(sm + NMS_SSA);
    unsigned* sup = (unsigned*)(sm + NMS_SUP);
    unsigned short* spos = (unsigned short*)(sm + NMS_SPOS);
    __shared__ int s_nsel, s_cnt, s_total;
    __shared__ int s_warp[32];

    int b = blockIdx.x, tid = threadIdx.x, bs = blockDim.x;
    for (int i = tid; i < PRE; i += bs) {
        float4 v = g_boxes[(size_t)b * PRE + i];
        sb[i] = v;
        sarea[i] = __fmul_rn(fmaxf(__fsub_rn(v.z, v.x), 0.f),
                             fmaxf(__fsub_rn(v.w, v.y), 0.f));
        lst0[i] = (unsigned short)i;
    }
    if (tid == 0) s_cnt = PRE;
    int cur = 0;
    float4* orow4 = (float4*)(out + (size_t)b * POST * 4);
    __syncthreads();

    int k = 0;
    while (k < POST) {
        int cnt = s_cnt;
        if (cnt == 0) break;
        unsigned short* lst = cur ? lst1 : lst0;
        int w = cnt < NMSW ? cnt : NMSW;

        // ---- stage window boxes contiguously ----
        if (tid < w) {
            int id = lst[tid];
            wb[tid] = sb[id];
            wa[tid] = sarea[id];
        }
        __syncthreads();

        // ---- suppression matrix: row p, word wd, bit q set (q>p) ----
        if (tid < w * 4) {
            int p = tid >> 2;
            int wd = tid & 3;
            unsigned m = 0;
            int qbase = wd << 5;
            if (qbase + 31 > p) {
                float4 bp = wb[p];
                float ap = wa[p];
#pragma unroll 8
                for (int t = 0; t < 32; t++) {
                    int q = qbase + t;
                    if (q > p && q < w && iou_sup(bp, ap, wb[q], wa[q]))
                        m |= 1u << t;
                }
            }
            sup[tid] = m;
        }
        __syncthreads();

        // ---- warp-parallel greedy chain (lanes 0-3 hold dead words) ----
        if (tid < 32) {
            int lane = tid;
            unsigned valid = 0;
            if (lane < 4) {
                int hi = w - (lane << 5);
                valid = (hi >= 32) ? 0xffffffffu
                                   : (hi > 0 ? ((1u << hi) - 1u) : 0u);
            }
            unsigned dead = 0;
            int nsel = 0;
            int lim = POST - k; if (lim > w) lim = w;
            for (;;) {
                unsigned alive = ~dead & valid;
                unsigned cand = alive ? (((unsigned)lane << 5) |
                                         (unsigned)(__ffs(alive) - 1))
                                      : 0xffffffffu;
                unsigned p = __reduce_min_sync(0xffffffffu, cand);
                if (p == 0xffffffffu) break;
                if (lane == 0) spos[nsel] = (unsigned short)p;
                nsel++;
                if (nsel >= lim) break;
                if (lane < 4) dead |= sup[((int)p << 2) + lane];
                if ((p >> 5) == (unsigned)lane) dead |= 1u << (p & 31);
            }
            if (lane == 0) s_nsel = nsel;
        }
        __syncthreads();
        int nsel = s_nsel;

        // ---- write outputs; gather selected boxes into ssel ----
        if (tid < nsel) {
            int p = spos[tid];
            float4 v = wb[p];
            ssel[tid] = v;
            ssa[tid] = wa[p];
            orow4[k + tid] = v;
        }
        k += nsel;
        if (k >= POST) break;
        __syncthreads();

        // ---- bulk sweep rest of list vs new selections (early exit) ----
        for (int pos = w + tid; pos < cnt; pos += bs) {
            int id = lst[pos];
            float4 bj = sb[id];
            float aj = sarea[id];
            bool dead = false;
            for (int s = 0; s < nsel; s++) {
                if (iou_sup(ssel[s], ssa[s], bj, aj)) { dead = true; break; }
            }
            if (dead) lst[pos] = DEADID;
        }
        __syncthreads();

        // ---- compact alive ids from [w,cnt) into the other buffer ----
        {
            int n = cnt - w;
            int per = (n + bs - 1) / bs;            // <= 6
            int st = w + tid * per;
            int en = st + per; if (en > cnt) en = cnt;
            unsigned short tmp[6];
            int c = 0;
            for (int p = st; p < en; p++) {
                unsigned short id = lst[p];
                if (id != DEADID) tmp[c++] = id;
            }
            int lane = tid & 31, wid = tid >> 5;
            int incl = c;
            for (int d = 1; d < 32; d <<= 1) {
                int t = __shfl_up_sync(0xffffffffu, incl, d);
                if (lane >= d) incl += t;
            }
            if (lane == 31) s_warp[wid] = incl;
            __syncthreads();
            if (wid == 0) {
                int v = s_warp[lane];
                int wi = v;
                for (int d = 1; d < 32; d <<= 1) {
                    int t = __shfl_up_sync(0xffffffffu, wi, d);
                    if (lane >= d) wi += t;
                }
                s_warp[lane] = wi - v;              // exclusive warp offset
                if (lane == 31) s_total = wi;
            }
            __syncthreads();
            int off = s_warp[wid] + (incl - c);
            unsigned short* dst = cur ? lst0 : lst1;
            for (int i2 = 0; i2 < c; i2++) dst[off + i2] = tmp[i2];
            __syncthreads();
            if (tid == 0) s_cnt = s_total;
            cur ^= 1;
            __syncthreads();
        }
    }
    // zero-pad remaining outputs (reference pads with zeros)
    for (int idx = k * 4 + tid; idx < POST * 4; idx += bs)
        out[(size_t)b * POST * 4 + idx] = 0.0f;
}

// ---------------- launch ---------------------------------------------------
extern "C" void kernel_launch(void* const* d_in, const int* in_sizes, int n_in,
                              void* d_out, int out_size) {
    const float* deltas = (const float*)d_in[0];   // (16,192,192,36)
    const float* scores = (const float*)d_in[1];   // (16,192,192,9)
    const float* banch  = (const float*)d_in[2];   // (9,4)
    float* out = (float*)d_out;                    // (16,1000,4)

    cudaFuncSetAttribute(k_sort_decode,
                         cudaFuncAttributeMaxDynamicSharedMemorySize,
                         CAP * (int)sizeof(unsigned long long));
    cudaFuncSetAttribute(k_nms,
                         cudaFuncAttributeMaxDynamicSharedMemorySize,
                         NMS_TOTAL);

    dim3 grid2(81, BATCH);                         // exactly 4 float4/thread
    k_hist<<<grid2, 256>>>(scores);
    k_thresh<<<BATCH, 256>>>();
    k_collect<<<grid2, 256>>>(scores);
    k_sort_decode<<<BATCH, 1024, CAP * (int)sizeof(unsigned long long)>>>(
        deltas, banch);
    k_nms<<<BATCH, 1024, NMS_TOTAL>>>(out);
}